// round 17
// baseline (speedup 1.0000x reference)
#include <cuda_runtime.h>
#include <cuda_fp16.h>
#include <cstdint>

#define N_NODES 50000
#define N_EDGES 800000
#define D 64
#define N_GRAPHS 512
#define N_LAYERS 3
#define HID_FC 64
#define N_CLASSES 10
#define SA 72      // smem stride in HALVES for A and W tiles: frag banks 4g+th
#define CAP 128    // adjacency bucket capacity per node (mean deg = 16)
#define MROWS 64   // rows per MLP block (4 warps x m16)
#define ZERO_OFF (N_NODES * 8u)  // uint4-row offset of the phantom zero row

// Scratch (device globals: no allocations allowed).
// +8 uint4 = one phantom row, zero-initialized at module load, NEVER written.
__device__ __half g_xh[(N_NODES + 1) * D];  // input x, fp16 (+zero row)
__device__ __half g_h[(N_NODES + 1) * D];   // layer activations (+zero row)
__device__ __half g_aggh[N_NODES * D];      // aggregated rows, fp16
__device__ unsigned int g_pool[N_GRAPHS * D];
__device__ int g_cur[N_NODES];
__device__ unsigned int g_adj[N_NODES * CAP];  // stores src*8 (uint4-row offset)
__device__ __half g_w1h[N_LAYERS * D * D];  // W1 fp16, TRANSPOSED: [out n][in k]
__device__ __half g_w2h[N_LAYERS * D * D];  // W2 fp16, TRANSPOSED: [out n][in k]

// ---------------------------------------------------------------------------
__device__ __forceinline__ uint32_t pack_h2(float lo, float hi) {
    __half2 h = __floats2half2_rn(lo, hi);
    return *reinterpret_cast<uint32_t*>(&h);
}

__device__ __forceinline__ __half2 u2h2(uint32_t u) {
    return *reinterpret_cast<const __half2*>(&u);
}

// accumulate QUAD of fp16 rows: two HADD2 levels, one cvt per quad
__device__ __forceinline__ void acc_quad(float* a, uint4 v0, uint4 v1,
                                         uint4 v2, uint4 v3) {
    float2 f;
    f = __half22float2(__hadd2(__hadd2(u2h2(v0.x), u2h2(v1.x)),
                               __hadd2(u2h2(v2.x), u2h2(v3.x))));
    a[0] += f.x; a[1] += f.y;
    f = __half22float2(__hadd2(__hadd2(u2h2(v0.y), u2h2(v1.y)),
                               __hadd2(u2h2(v2.y), u2h2(v3.y))));
    a[2] += f.x; a[3] += f.y;
    f = __half22float2(__hadd2(__hadd2(u2h2(v0.z), u2h2(v1.z)),
                               __hadd2(u2h2(v2.z), u2h2(v3.z))));
    a[4] += f.x; a[5] += f.y;
    f = __half22float2(__hadd2(__hadd2(u2h2(v0.w), u2h2(v1.w)),
                               __hadd2(u2h2(v2.w), u2h2(v3.w))));
    a[6] += f.x; a[7] += f.y;
}

// ---------------------------------------------------------------------------
// Setup (once per replay): weights -> fp16 transposed, pool init, x -> fp16,
// adjacency fill with PRE-MULTIPLIED offsets (src*8 = uint4-row index).
// ---------------------------------------------------------------------------
__global__ void setup_kernel(const float* __restrict__ x,
                             const float* __restrict__ convW1,
                             const float* __restrict__ convW2,
                             const int* __restrict__ src,
                             const int* __restrict__ dst) {
    int i = blockIdx.x * blockDim.x + threadIdx.x;
    if (i < N_LAYERS * D * D) {
        int l = i >> 12;
        int rem = i & 4095;
        int n = rem >> 6;   // output col
        int k = rem & 63;   // input row
        g_w1h[i] = __float2half(convW1[(l << 12) + (k << 6) + n]);
        g_w2h[i] = __float2half(convW2[(l << 12) + (k << 6) + n]);
    }
    if (i < N_GRAPHS * D) g_pool[i] = 0x00800000u;  // encode(-FLT_MAX)
    if (i < N_NODES * D / 2) {
        float2 v = reinterpret_cast<const float2*>(x)[i];
        reinterpret_cast<__half2*>(g_xh)[i] = __floats2half2_rn(v.x, v.y);
    }
    if (i < N_EDGES / 8) {
        int e = i * 8;
        int4 d0 = *reinterpret_cast<const int4*>(dst + e);
        int4 d1 = *reinterpret_cast<const int4*>(dst + e + 4);
        int4 s0 = *reinterpret_cast<const int4*>(src + e);
        int4 s1 = *reinterpret_cast<const int4*>(src + e + 4);
        int p0 = atomicAdd(&g_cur[d0.x], 1);
        int p1 = atomicAdd(&g_cur[d0.y], 1);
        int p2 = atomicAdd(&g_cur[d0.z], 1);
        int p3 = atomicAdd(&g_cur[d0.w], 1);
        int p4 = atomicAdd(&g_cur[d1.x], 1);
        int p5 = atomicAdd(&g_cur[d1.y], 1);
        int p6 = atomicAdd(&g_cur[d1.z], 1);
        int p7 = atomicAdd(&g_cur[d1.w], 1);
        g_adj[d0.x * CAP + p0] = (unsigned int)s0.x * 8u;
        g_adj[d0.y * CAP + p1] = (unsigned int)s0.y * 8u;
        g_adj[d0.z * CAP + p2] = (unsigned int)s0.z * 8u;
        g_adj[d0.w * CAP + p3] = (unsigned int)s0.w * 8u;
        g_adj[d1.x * CAP + p4] = (unsigned int)s1.x * 8u;
        g_adj[d1.y * CAP + p5] = (unsigned int)s1.y * 8u;
        g_adj[d1.z * CAP + p6] = (unsigned int)s1.z * 8u;
        g_adj[d1.w * CAP + p7] = (unsigned int)s1.w * 8u;
    }
}

// ---------------------------------------------------------------------------
// Gather aggregation: aggh[n] = fp16(h[n] + sum_{j in N(n)} h[j]); h is fp16.
// 8 threads per node, one uint4 per lane. BRANCH-FREE: out-of-range lanes
// point at the phantom zero row, so every round is two straight acc_quads.
// Index loads software-pipelined; offsets pre-multiplied (32-bit adds only).
// ---------------------------------------------------------------------------
__global__ __launch_bounds__(256, 6) void gather_kernel(const uint4* __restrict__ hin4,
                                                        uint4* __restrict__ aggh4) {
    unsigned int gid = blockIdx.x * 256u + threadIdx.x;
    unsigned int node = gid >> 3;
    unsigned int lane = gid & 7u;
    if (node >= N_NODES) return;
    unsigned int hm = 0xFFu << (threadIdx.x & 24);  // this 8-lane segment

    unsigned int self_off = node * 8u + lane;
    int cnt = g_cur[node];
    const unsigned int* adj = g_adj + node * CAP;

    // prologue: first idx batch in flight while the self row loads
    unsigned int idx = ((int)lane < cnt) ? __ldg(adj + lane) : ZERO_OFF;

    float a[8];
    {
        uint4 s = hin4[self_off];  // self term (eps = 0)
        float2 f;
        f = __half22float2(u2h2(s.x)); a[0] = f.x; a[1] = f.y;
        f = __half22float2(u2h2(s.y)); a[2] = f.x; a[3] = f.y;
        f = __half22float2(u2h2(s.z)); a[4] = f.x; a[5] = f.y;
        f = __half22float2(u2h2(s.w)); a[6] = f.x; a[7] = f.y;
    }

    for (int base = 0; base < cnt; base += 8) {
        // pipeline: issue next round's idx load before consuming this round
        int nxt = base + 8 + (int)lane;
        unsigned int idx_next = (nxt < cnt) ? __ldg(adj + nxt) : ZERO_OFF;

#pragma unroll
        for (int j = 0; j < 8; j += 4) {
            unsigned int o0 = __shfl_sync(hm, idx, j + 0, 8) + lane;
            unsigned int o1 = __shfl_sync(hm, idx, j + 1, 8) + lane;
            unsigned int o2 = __shfl_sync(hm, idx, j + 2, 8) + lane;
            unsigned int o3 = __shfl_sync(hm, idx, j + 3, 8) + lane;
            uint4 v0 = hin4[o0];
            uint4 v1 = hin4[o1];
            uint4 v2 = hin4[o2];
            uint4 v3 = hin4[o3];
            acc_quad(a, v0, v1, v2, v3);
        }
        idx = idx_next;
    }

    uint4 o;
    o.x = pack_h2(a[0], a[1]);
    o.y = pack_h2(a[2], a[3]);
    o.z = pack_h2(a[4], a[5]);
    o.w = pack_h2(a[6], a[7]);
    aggh4[self_off] = o;
}

// ---------------------------------------------------------------------------
// FP16 tensor-core fused MLP: h_out = relu(agg @ W1 + b1) @ W2 + b2
// mma.sync m16n8k16 f16.f16.f32. Block = 128 threads (4 warps) = 64 rows;
// grid 782 = single fully-resident wave at 6 blocks/SM (24 warps/SM).
// W stored transposed [n][k]; GEMM2 A-frags == GEMM1 C-frags (same thread).
// mode 0: write hout (fp16); mode 1: fused global-max-pool into g_pool
// ---------------------------------------------------------------------------
__device__ __forceinline__ void mma_f16(float* c, uint32_t a0, uint32_t a1,
                                        uint32_t a2, uint32_t a3,
                                        uint32_t b0, uint32_t b1) {
    asm volatile(
        "mma.sync.aligned.m16n8k16.row.col.f32.f16.f16.f32 "
        "{%0,%1,%2,%3}, {%4,%5,%6,%7}, {%8,%9}, {%0,%1,%2,%3};"
        : "+f"(c[0]), "+f"(c[1]), "+f"(c[2]), "+f"(c[3])
        : "r"(a0), "r"(a1), "r"(a2), "r"(a3), "r"(b0), "r"(b1));
}

__global__ __launch_bounds__(128, 6) void mlp_tc_kernel(const uint4* __restrict__ xinh,
                                                        const __half* __restrict__ W1h,
                                                        const float* __restrict__ b1,
                                                        const __half* __restrict__ W2h,
                                                        const float* __restrict__ b2,
                                                        __half* __restrict__ hout,
                                                        const int* __restrict__ batch,
                                                        int mode) {
    __shared__ __half As[MROWS * SA];   // A tile (fp16)
    __shared__ __half Ws1[D * SA];      // W1^T (fp16)
    __shared__ __half Ws2[D * SA];      // W2^T (fp16)
    __shared__ float b1s[D];
    __shared__ float b2s[D];

    int tid = threadIdx.x;
    int warp = tid >> 5;
    int lane = tid & 31;
    int g = lane >> 2;   // group 0..7
    int th = lane & 3;   // thread-in-group 0..3
    int arow = warp * 16;
    int row0 = blockIdx.x * MROWS;

    // ---- stage A (64 rows x 8 uint4) + W1^T + W2^T ----
    for (int i = tid; i < MROWS * 8; i += 128) {
        int r = i >> 3;
        int c8 = (i & 7) << 3;
        uint4 t = make_uint4(0u, 0u, 0u, 0u);
        if (row0 + r < N_NODES)
            t = xinh[(size_t)(row0 + r) * 8 + (i & 7)];
        *reinterpret_cast<uint4*>(&As[r * SA + c8]) = t;
    }
    for (int i = tid; i < D * 8; i += 128) {
        int n = i >> 3;
        int c8 = (i & 7) << 3;
        uint4 t1 = reinterpret_cast<const uint4*>(W1h)[i];
        uint4 t2 = reinterpret_cast<const uint4*>(W2h)[i];
        *reinterpret_cast<uint4*>(&Ws1[n * SA + c8]) = t1;
        *reinterpret_cast<uint4*>(&Ws2[n * SA + c8]) = t2;
    }
    if (tid < D) { b1s[tid] = b1[tid]; b2s[tid] = b2[tid]; }
    __syncthreads();

    // ---- GEMM 1: acc = A @ W1  (4 k-chunks of 16) ----
    float acc[8][4];
#pragma unroll
    for (int n = 0; n < 8; n++)
#pragma unroll
        for (int j = 0; j < 4; j++) acc[n][j] = 0.f;

#pragma unroll
    for (int kc = 0; kc < 4; kc++) {
        uint32_t a0 = *reinterpret_cast<const uint32_t*>(&As[(arow + g) * SA + kc * 16 + 2 * th]);
        uint32_t a1 = *reinterpret_cast<const uint32_t*>(&As[(arow + g + 8) * SA + kc * 16 + 2 * th]);
        uint32_t a2 = *reinterpret_cast<const uint32_t*>(&As[(arow + g) * SA + kc * 16 + 2 * th + 8]);
        uint32_t a3 = *reinterpret_cast<const uint32_t*>(&As[(arow + g + 8) * SA + kc * 16 + 2 * th + 8]);
#pragma unroll
        for (int n = 0; n < 8; n++) {
            uint32_t bf0 = *reinterpret_cast<const uint32_t*>(&Ws1[(n * 8 + g) * SA + kc * 16 + 2 * th]);
            uint32_t bf1 = *reinterpret_cast<const uint32_t*>(&Ws1[(n * 8 + g) * SA + kc * 16 + 2 * th + 8]);
            mma_f16(acc[n], a0, a1, a2, a3, bf0, bf1);
        }
    }

    // ---- bias + relu (acc becomes T, fp32) ----
#pragma unroll
    for (int n = 0; n < 8; n++) {
        int c = n * 8 + 2 * th;
        acc[n][0] = fmaxf(acc[n][0] + b1s[c], 0.f);
        acc[n][1] = fmaxf(acc[n][1] + b1s[c + 1], 0.f);
        acc[n][2] = fmaxf(acc[n][2] + b1s[c], 0.f);
        acc[n][3] = fmaxf(acc[n][3] + b1s[c + 1], 0.f);
    }

    // ---- GEMM 2: acc2 = T @ W2; A-frags = own C-frags, cvt+pack only ----
    float acc2[8][4];
#pragma unroll
    for (int n = 0; n < 8; n++)
#pragma unroll
        for (int j = 0; j < 4; j++) acc2[n][j] = 0.f;

#pragma unroll
    for (int kc = 0; kc < 4; kc++) {
        uint32_t a0 = pack_h2(acc[2 * kc][0], acc[2 * kc][1]);
        uint32_t a1 = pack_h2(acc[2 * kc][2], acc[2 * kc][3]);
        uint32_t a2 = pack_h2(acc[2 * kc + 1][0], acc[2 * kc + 1][1]);
        uint32_t a3 = pack_h2(acc[2 * kc + 1][2], acc[2 * kc + 1][3]);
#pragma unroll
        for (int n = 0; n < 8; n++) {
            uint32_t bf0 = *reinterpret_cast<const uint32_t*>(&Ws2[(n * 8 + g) * SA + kc * 16 + 2 * th]);
            uint32_t bf1 = *reinterpret_cast<const uint32_t*>(&Ws2[(n * 8 + g) * SA + kc * 16 + 2 * th + 8]);
            mma_f16(acc2[n], a0, a1, a2, a3, bf0, bf1);
        }
    }

    // ---- bias + output ----
    int r0 = row0 + arow + g;
    int r1 = r0 + 8;
    bool v0 = (r0 < N_NODES);
    bool v1 = (r1 < N_NODES);

    if (mode == 0) {
#pragma unroll
        for (int n = 0; n < 8; n++) {
            int c = n * 8 + 2 * th;
            if (v0) {
                __half2 o = __floats2half2_rn(acc2[n][0] + b2s[c], acc2[n][1] + b2s[c + 1]);
                *reinterpret_cast<__half2*>(&hout[(size_t)r0 * D + c]) = o;
            }
            if (v1) {
                __half2 o = __floats2half2_rn(acc2[n][2] + b2s[c], acc2[n][3] + b2s[c + 1]);
                *reinterpret_cast<__half2*>(&hout[(size_t)r1 * D + c]) = o;
            }
        }
    } else {
        int gb0 = v0 ? batch[r0] : 0;
        int gb1 = v1 ? batch[r1] : 0;
        unsigned int* p0 = g_pool + (size_t)gb0 * D;
        unsigned int* p1 = g_pool + (size_t)gb1 * D;
#pragma unroll
        for (int n = 0; n < 8; n++) {
            int c = n * 8 + 2 * th;
#pragma unroll
            for (int j = 0; j < 4; j++) {
                float val = acc2[n][j] + b2s[c + (j & 1)];
                unsigned int bits = __float_as_uint(val);
                unsigned int enc = (bits & 0x80000000u) ? ~bits : (bits | 0x80000000u);
                if (j < 2) { if (v0) atomicMax(&p0[c + (j & 1)], enc); }
                else       { if (v1) atomicMax(&p1[c + (j & 1)], enc); }
            }
        }
    }
}

// ---------------------------------------------------------------------------
// FC head + log_softmax. One block (64 threads) per graph.
// ---------------------------------------------------------------------------
__global__ __launch_bounds__(64) void fc_kernel(const float* __restrict__ fcW1,
                                                const float* __restrict__ fcb1,
                                                const float* __restrict__ fcW2,
                                                const float* __restrict__ fcb2,
                                                float* __restrict__ out) {
    __shared__ float xr[D];
    __shared__ float hid[HID_FC];
    __shared__ float logits[N_CLASSES];
    __shared__ float m_s, lse_s;

    int g = blockIdx.x;
    int t = threadIdx.x;

    unsigned int e = g_pool[(size_t)g * D + t];
    unsigned int u = (e & 0x80000000u) ? (e & 0x7FFFFFFFu) : ~e;
    xr[t] = __uint_as_float(u);
    __syncthreads();

    float a = fcb1[t];
#pragma unroll
    for (int k = 0; k < D; k++) a += xr[k] * fcW1[k * HID_FC + t];
    hid[t] = fmaxf(a, 0.0f);
    __syncthreads();

    if (t < N_CLASSES) {
        float a2 = fcb2[t];
#pragma unroll
        for (int k = 0; k < HID_FC; k++) a2 += hid[k] * fcW2[k * N_CLASSES + t];
        logits[t] = a2;
    }
    __syncthreads();

    if (t == 0) {
        float m = logits[0];
#pragma unroll
        for (int j = 1; j < N_CLASSES; j++) m = fmaxf(m, logits[j]);
        float s = 0.0f;
#pragma unroll
        for (int j = 0; j < N_CLASSES; j++) s += expf(logits[j] - m);
        m_s = m;
        lse_s = logf(s);
    }
    __syncthreads();

    if (t < N_CLASSES) out[(size_t)g * N_CLASSES + t] = logits[t] - m_s - lse_s;
}

// ---------------------------------------------------------------------------
extern "C" void kernel_launch(void* const* d_in, const int* in_sizes, int n_in,
                              void* d_out, int out_size) {
    const float* x      = (const float*)d_in[0];
    const float* convW1 = (const float*)d_in[1];
    const float* convb1 = (const float*)d_in[2];
    const float* convW2 = (const float*)d_in[3];
    const float* convb2 = (const float*)d_in[4];
    const float* fcW1   = (const float*)d_in[5];
    const float* fcb1   = (const float*)d_in[6];
    const float* fcW2   = (const float*)d_in[7];
    const float* fcb2   = (const float*)d_in[8];
    const int* edge_index = (const int*)d_in[9];
    const int* batch      = (const int*)d_in[10];
    float* out = (float*)d_out;

    const int* src = edge_index;
    const int* dst = edge_index + N_EDGES;

    __half* xh_ptr = nullptr;
    __half* h_ptr = nullptr;
    __half* aggh_ptr = nullptr;
    int* cur_ptr = nullptr;
    __half* w1h_ptr = nullptr;
    __half* w2h_ptr = nullptr;
    cudaGetSymbolAddress((void**)&xh_ptr, g_xh);
    cudaGetSymbolAddress((void**)&h_ptr, g_h);
    cudaGetSymbolAddress((void**)&aggh_ptr, g_aggh);
    cudaGetSymbolAddress((void**)&cur_ptr, g_cur);
    cudaGetSymbolAddress((void**)&w1h_ptr, g_w1h);
    cudaGetSymbolAddress((void**)&w2h_ptr, g_w2h);

    const int gather_blocks = (N_NODES * 8 + 255) / 256;     // 1563
    const int mlp_blocks = (N_NODES + MROWS - 1) / MROWS;    // 782
    const int setup_blocks = (N_NODES * D / 2 + 255) / 256;  // covers all setup jobs

    // ---- per-replay setup ----
    cudaMemsetAsync(cur_ptr, 0, (size_t)N_NODES * sizeof(int));
    setup_kernel<<<setup_blocks, 256>>>(x, convW1, convW2, src, dst);

    // ---- 3 GIN layers ----
    for (int l = 0; l < N_LAYERS; l++) {
        const __half* hin = (l == 0) ? xh_ptr : h_ptr;
        int mode = (l == N_LAYERS - 1) ? 1 : 0;
        gather_kernel<<<gather_blocks, 256>>>((const uint4*)hin, (uint4*)aggh_ptr);
        mlp_tc_kernel<<<mlp_blocks, 128>>>((const uint4*)aggh_ptr,
                                           w1h_ptr + (size_t)l * D * D, convb1 + (size_t)l * D,
                                           w2h_ptr + (size_t)l * D * D, convb2 + (size_t)l * D,
                                           h_ptr, batch, mode);
    }

    fc_kernel<<<N_GRAPHS, 64>>>(fcW1, fcb1, fcW2, fcb2, out);
}